// round 3
// baseline (speedup 1.0000x reference)
#include <cuda_runtime.h>
#include <cstdint>

#define NMAX   50000
#define DIM    64

// Scratch (allocation-free rule: __device__ globals)
__device__ float g_agg[(size_t)NMAX * DIM];
__device__ int   g_deg[NMAX];

// ---------------------------------------------------------------------------
// Kernel 1: zero the accumulators (must run every launch — deterministic).
// ---------------------------------------------------------------------------
__global__ void zero_kernel(int n) {
    int i = blockIdx.x * blockDim.x + threadIdx.x;
    int n4 = n * (DIM / 4);                  // number of float4 in agg
    if (i < n4) ((float4*)g_agg)[i] = make_float4(0.f, 0.f, 0.f, 0.f);
    if (i < n)  g_deg[i] = 0;
}

// ---------------------------------------------------------------------------
// Kernel 2: edge aggregation. 16 threads per edge, float4 chunks.
//   agg[row] += x[col]   (vector RED, no return)
//   deg[row] += 1        (int RED)
// edge_index is int32 (JAX x64 disabled downcasts int64 -> int32).
// ---------------------------------------------------------------------------
__global__ __launch_bounds__(256) void edge_kernel(
    const float* __restrict__ x,
    const int* __restrict__ ei,
    int E)
{
    int gid = blockIdx.x * blockDim.x + threadIdx.x;
    int e = gid >> 4;
    int t = gid & 15;
    if (e >= E) return;

    int row = ei[e];
    int col = ei[E + e];

    const float4 v = *(const float4*)(x + (size_t)col * DIM + t * 4);
    float* dst = g_agg + (size_t)row * DIM + t * 4;

    asm volatile("red.global.add.v4.f32 [%0], {%1, %2, %3, %4};"
                 :: "l"(dst), "f"(v.x), "f"(v.y), "f"(v.z), "f"(v.w)
                 : "memory");

    if (t == 0) atomicAdd(g_deg + row, 1);
}

// ---------------------------------------------------------------------------
// Kernel 3: out = (agg / (deg+1e-6)) @ W^T + b
// Block: 64 nodes x 64 cols, 256 threads, each thread 4 nodes x 4 cols.
// ---------------------------------------------------------------------------
__global__ __launch_bounds__(256) void out_kernel(
    const float* __restrict__ W,   // [64 out][64 in], row-major
    const float* __restrict__ b,   // [64]
    float* __restrict__ out,       // [n][64]
    int n)
{
    __shared__ float sW[64 * 68];  // transposed: sW[k*68 + j] = W[j][k], padded
    __shared__ float sA[64 * 68];  // agg tile: sA[node*68 + k], padded
    __shared__ float sB[64];

    const int tid  = threadIdx.x;
    const int base = blockIdx.x * 64;

    // Load W transposed (coalesced global read, tiny)
    for (int idx = tid; idx < 64 * 64; idx += 256) {
        int j = idx >> 6;      // out index
        int k = idx & 63;      // in index
        sW[k * 68 + j] = W[idx];
    }
    if (tid < 64) sB[tid] = b[tid];

    // Load agg tile (float4, coalesced), bounds-guarded
    #pragma unroll
    for (int p = 0; p < 4; p++) {
        int idx  = tid + p * 256;          // 0..1023
        int nd   = idx >> 4;               // local node 0..63
        int ch   = idx & 15;               // float4 chunk 0..15
        int node = base + nd;
        float4 v = make_float4(0.f, 0.f, 0.f, 0.f);
        if (node < n)
            v = *(const float4*)&g_agg[(size_t)node * DIM + ch * 4];
        *(float4*)&sA[nd * 68 + ch * 4] = v;
    }
    __syncthreads();

    const int tx = tid & 15;   // col group (4 cols at tx*4)
    const int ty = tid >> 4;   // node group (4 nodes at ty*4)

    float acc[4][4];
    #pragma unroll
    for (int i = 0; i < 4; i++)
        #pragma unroll
        for (int c = 0; c < 4; c++)
            acc[i][c] = 0.f;

    #pragma unroll
    for (int k = 0; k < 64; k += 4) {
        float4 wv0 = *(const float4*)&sW[(k + 0) * 68 + tx * 4];
        float4 wv1 = *(const float4*)&sW[(k + 1) * 68 + tx * 4];
        float4 wv2 = *(const float4*)&sW[(k + 2) * 68 + tx * 4];
        float4 wv3 = *(const float4*)&sW[(k + 3) * 68 + tx * 4];
        #pragma unroll
        for (int i = 0; i < 4; i++) {
            float4 av = *(const float4*)&sA[(ty * 4 + i) * 68 + k];
            acc[i][0] += av.x * wv0.x + av.y * wv1.x + av.z * wv2.x + av.w * wv3.x;
            acc[i][1] += av.x * wv0.y + av.y * wv1.y + av.z * wv2.y + av.w * wv3.y;
            acc[i][2] += av.x * wv0.z + av.y * wv1.z + av.z * wv2.z + av.w * wv3.z;
            acc[i][3] += av.x * wv0.w + av.y * wv1.w + av.z * wv2.w + av.w * wv3.w;
        }
    }

    #pragma unroll
    for (int i = 0; i < 4; i++) {
        int node = base + ty * 4 + i;
        if (node < n) {
            float inv = 1.0f / ((float)g_deg[node] + 1e-6f);
            float4 o;
            o.x = acc[i][0] * inv + sB[tx * 4 + 0];
            o.y = acc[i][1] * inv + sB[tx * 4 + 1];
            o.z = acc[i][2] * inv + sB[tx * 4 + 2];
            o.w = acc[i][3] * inv + sB[tx * 4 + 3];
            *(float4*)&out[(size_t)node * DIM + tx * 4] = o;
        }
    }
}

// ---------------------------------------------------------------------------
// kernel_launch — inputs per metadata: x [N*64 f32], edge_index [2*E i32],
// W [64*64 f32], b [64 f32]; output [N*64 f32].
// ---------------------------------------------------------------------------
extern "C" void kernel_launch(void* const* d_in, const int* in_sizes, int n_in,
                              void* d_out, int out_size) {
    const float* x  = (const float*)d_in[0];
    const int*   ei = (const int*)d_in[1];
    const float* W  = (const float*)d_in[2];
    const float* b  = (const float*)d_in[3];
    float*       out = (float*)d_out;

    int n = in_sizes[0] / DIM;       // 50000
    int E = in_sizes[1] / 2;         // 800000

    // zero accumulators
    {
        int n4 = n * (DIM / 4);
        int blocks = (n4 + 255) / 256;
        zero_kernel<<<blocks, 256>>>(n);
    }
    // aggregate
    {
        long long total = (long long)E * 16;
        int blocks = (int)((total + 255) / 256);
        edge_kernel<<<blocks, 256>>>(x, ei, E);
    }
    // linear + normalize
    {
        int blocks = (n + 63) / 64;
        out_kernel<<<blocks, 256>>>(W, b, out, n);
    }
}

// round 4
// speedup vs baseline: 1.0575x; 1.0575x over previous
#include <cuda_runtime.h>
#include <cstdint>

#define DIM     64
#define NPAD    50176          // 196 * 256, >= N, padded for clean scans
#define NBLK    196            // NPAD / 256
#define EMAX    800000

// Scratch (allocation-free rule: __device__ globals)
__device__ int   g_deg[NPAD];
__device__ int   g_start[NPAD];
__device__ int   g_cursor[NPAD];
__device__ int   g_cols[EMAX];
__device__ float g_agg[(size_t)NPAD * DIM];
__device__ int   g_bsum[256];
__device__ int   g_boff[256];

// ---------------------------------------------------------------------------
// 1. zero degree histogram (incl. padding)
// ---------------------------------------------------------------------------
__global__ void k_zero() {
    int i = blockIdx.x * blockDim.x + threadIdx.x;
    if (i < NPAD) g_deg[i] = 0;
}

// ---------------------------------------------------------------------------
// 2. histogram of destination rows
// ---------------------------------------------------------------------------
__global__ __launch_bounds__(256) void k_hist(const int* __restrict__ ei, int E) {
    int i = blockIdx.x * blockDim.x + threadIdx.x;
    if (i < E) atomicAdd(&g_deg[ei[i]], 1);
}

// ---------------------------------------------------------------------------
// 3. per-256-block sums of g_deg
// ---------------------------------------------------------------------------
__global__ __launch_bounds__(256) void k_blockred() {
    __shared__ int s[256];
    int tid = threadIdx.x;
    s[tid] = g_deg[blockIdx.x * 256 + tid];
    __syncthreads();
    #pragma unroll
    for (int off = 128; off > 0; off >>= 1) {
        if (tid < off) s[tid] += s[tid + off];
        __syncthreads();
    }
    if (tid == 0) g_bsum[blockIdx.x] = s[0];
}

// ---------------------------------------------------------------------------
// 4. exclusive scan of the 196 block sums (single block)
// ---------------------------------------------------------------------------
__global__ __launch_bounds__(256) void k_scanblocks() {
    __shared__ int s[256];
    int tid = threadIdx.x;
    int v = (tid < NBLK) ? g_bsum[tid] : 0;
    s[tid] = v;
    __syncthreads();
    #pragma unroll
    for (int off = 1; off < 256; off <<= 1) {
        int t = (tid >= off) ? s[tid - off] : 0;
        __syncthreads();
        s[tid] += t;
        __syncthreads();
    }
    g_boff[tid] = s[tid] - v;   // exclusive
}

// ---------------------------------------------------------------------------
// 5. per-element exclusive scan within each block + block offset -> start/cursor
// ---------------------------------------------------------------------------
__global__ __launch_bounds__(256) void k_makestart() {
    __shared__ int s[256];
    int tid = threadIdx.x;
    int i = blockIdx.x * 256 + tid;
    int c = g_deg[i];
    s[tid] = c;
    __syncthreads();
    #pragma unroll
    for (int off = 1; off < 256; off <<= 1) {
        int t = (tid >= off) ? s[tid - off] : 0;
        __syncthreads();
        s[tid] += t;
        __syncthreads();
    }
    int start = g_boff[blockIdx.x] + s[tid] - c;   // exclusive
    g_start[i]  = start;
    g_cursor[i] = start;
}

// ---------------------------------------------------------------------------
// 6. scatter source cols into CSR order
// ---------------------------------------------------------------------------
__global__ __launch_bounds__(256) void k_scatter(const int* __restrict__ ei, int E) {
    int i = blockIdx.x * blockDim.x + threadIdx.x;
    if (i < E) {
        int row = ei[i];
        int col = ei[E + i];
        int slot = atomicAdd(&g_cursor[row], 1);
        g_cols[slot] = col;
    }
}

// ---------------------------------------------------------------------------
// 7. gather-sum: 16 threads per row, float4 accumulators, plain stores.
// ---------------------------------------------------------------------------
__global__ __launch_bounds__(256) void k_gather(const float* __restrict__ x, int n) {
    int row = blockIdx.x * 16 + (threadIdx.x >> 4);
    int t   = threadIdx.x & 15;
    if (row >= n) return;

    int s = g_start[row];
    int c = g_deg[row];

    float4 acc = make_float4(0.f, 0.f, 0.f, 0.f);
    int j = 0;
    for (; j + 4 <= c; j += 4) {
        int c0 = g_cols[s + j + 0];
        int c1 = g_cols[s + j + 1];
        int c2 = g_cols[s + j + 2];
        int c3 = g_cols[s + j + 3];
        float4 v0 = *(const float4*)(x + (size_t)c0 * DIM + t * 4);
        float4 v1 = *(const float4*)(x + (size_t)c1 * DIM + t * 4);
        float4 v2 = *(const float4*)(x + (size_t)c2 * DIM + t * 4);
        float4 v3 = *(const float4*)(x + (size_t)c3 * DIM + t * 4);
        acc.x += v0.x + v1.x + v2.x + v3.x;
        acc.y += v0.y + v1.y + v2.y + v3.y;
        acc.z += v0.z + v1.z + v2.z + v3.z;
        acc.w += v0.w + v1.w + v2.w + v3.w;
    }
    for (; j < c; j++) {
        int cc = g_cols[s + j];
        float4 v = *(const float4*)(x + (size_t)cc * DIM + t * 4);
        acc.x += v.x; acc.y += v.y; acc.z += v.z; acc.w += v.w;
    }
    *(float4*)&g_agg[(size_t)row * DIM + t * 4] = acc;
}

// ---------------------------------------------------------------------------
// 8. out = (agg / (deg+1e-6)) @ W^T + b
// ---------------------------------------------------------------------------
__global__ __launch_bounds__(256) void out_kernel(
    const float* __restrict__ W,
    const float* __restrict__ b,
    float* __restrict__ out,
    int n)
{
    __shared__ float sW[64 * 68];
    __shared__ float sA[64 * 68];
    __shared__ float sB[64];

    const int tid  = threadIdx.x;
    const int base = blockIdx.x * 64;

    for (int idx = tid; idx < 64 * 64; idx += 256) {
        int j = idx >> 6;
        int k = idx & 63;
        sW[k * 68 + j] = W[idx];
    }
    if (tid < 64) sB[tid] = b[tid];

    #pragma unroll
    for (int p = 0; p < 4; p++) {
        int idx  = tid + p * 256;
        int nd   = idx >> 4;
        int ch   = idx & 15;
        int node = base + nd;
        float4 v = make_float4(0.f, 0.f, 0.f, 0.f);
        if (node < n)
            v = *(const float4*)&g_agg[(size_t)node * DIM + ch * 4];
        *(float4*)&sA[nd * 68 + ch * 4] = v;
    }
    __syncthreads();

    const int tx = tid & 15;
    const int ty = tid >> 4;

    float acc[4][4];
    #pragma unroll
    for (int i = 0; i < 4; i++)
        #pragma unroll
        for (int c = 0; c < 4; c++)
            acc[i][c] = 0.f;

    #pragma unroll
    for (int k = 0; k < 64; k += 4) {
        float4 wv0 = *(const float4*)&sW[(k + 0) * 68 + tx * 4];
        float4 wv1 = *(const float4*)&sW[(k + 1) * 68 + tx * 4];
        float4 wv2 = *(const float4*)&sW[(k + 2) * 68 + tx * 4];
        float4 wv3 = *(const float4*)&sW[(k + 3) * 68 + tx * 4];
        #pragma unroll
        for (int i = 0; i < 4; i++) {
            float4 av = *(const float4*)&sA[(ty * 4 + i) * 68 + k];
            acc[i][0] += av.x * wv0.x + av.y * wv1.x + av.z * wv2.x + av.w * wv3.x;
            acc[i][1] += av.x * wv0.y + av.y * wv1.y + av.z * wv2.y + av.w * wv3.y;
            acc[i][2] += av.x * wv0.z + av.y * wv1.z + av.z * wv2.z + av.w * wv3.z;
            acc[i][3] += av.x * wv0.w + av.y * wv1.w + av.z * wv2.w + av.w * wv3.w;
        }
    }

    #pragma unroll
    for (int i = 0; i < 4; i++) {
        int node = base + ty * 4 + i;
        if (node < n) {
            float inv = 1.0f / ((float)g_deg[node] + 1e-6f);
            float4 o;
            o.x = acc[i][0] * inv + sB[tx * 4 + 0];
            o.y = acc[i][1] * inv + sB[tx * 4 + 1];
            o.z = acc[i][2] * inv + sB[tx * 4 + 2];
            o.w = acc[i][3] * inv + sB[tx * 4 + 3];
            *(float4*)&out[(size_t)node * DIM + tx * 4] = o;
        }
    }
}

// ---------------------------------------------------------------------------
// kernel_launch — inputs: x [N*64 f32], edge_index [2*E i32], W [64*64 f32],
// b [64 f32]; output [N*64 f32].
// ---------------------------------------------------------------------------
extern "C" void kernel_launch(void* const* d_in, const int* in_sizes, int n_in,
                              void* d_out, int out_size) {
    const float* x  = (const float*)d_in[0];
    const int*   ei = (const int*)d_in[1];
    const float* W  = (const float*)d_in[2];
    const float* b  = (const float*)d_in[3];
    float*       out = (float*)d_out;

    int n = in_sizes[0] / DIM;       // 50000
    int E = in_sizes[1] / 2;         // 800000

    int eblocks = (E + 255) / 256;

    k_zero<<<NBLK, 256>>>();
    k_hist<<<eblocks, 256>>>(ei, E);
    k_blockred<<<NBLK, 256>>>();
    k_scanblocks<<<1, 256>>>();
    k_makestart<<<NBLK, 256>>>();
    k_scatter<<<eblocks, 256>>>(ei, E);
    k_gather<<<(n + 15) / 16, 256>>>(x, n);
    out_kernel<<<(n + 63) / 64, 256>>>(W, b, out, n);
}